// round 1
// baseline (speedup 1.0000x reference)
#include <cuda_runtime.h>
#include <cuda_bf16.h>

// Problem constants
#define Bc   8
#define Sc   4096
#define Dc   1024
#define Mtot 32768            // B*S
#define NE   33554432         // Mtot*Dc elements
#define NC   32               // scan chunks
#define LC   128              // chunk length (NC*LC == Sc)

// -------- scratch (device globals: allocation-free) --------
__device__ __align__(16) float g_xg[NE];
__device__ __align__(16) float g_u [NE];   // u, then hf (in place)
__device__ __align__(16) float g_v [NE];
__device__ __align__(16) float g_p [NE];   // gate_x pre -> scaled_in -> hb (in place)
__device__ __align__(16) float g_q [NE];   // gate_a pre -> a
__device__ float g_cV[Bc*NC*Dc];
__device__ float g_cP[Bc*NC*Dc];
__device__ float g_cI[Bc*NC*Dc];

// ================= helpers =================
__device__ __forceinline__ float tf32r(float x) {
    unsigned u; asm("cvt.rna.tf32.f32 %0, %1;" : "=r"(u) : "f"(x));
    return __uint_as_float(u);
}
__device__ __forceinline__ void mma8(float* c, const unsigned* a, const unsigned* b) {
    asm volatile(
        "mma.sync.aligned.m16n8k8.row.col.f32.tf32.tf32.f32 "
        "{%0,%1,%2,%3}, {%4,%5,%6,%7}, {%8,%9}, {%0,%1,%2,%3};\n"
        : "+f"(c[0]), "+f"(c[1]), "+f"(c[2]), "+f"(c[3])
        : "r"(a[0]), "r"(a[1]), "r"(a[2]), "r"(a[3]), "r"(b[0]), "r"(b[1]));
}
__device__ __forceinline__ float gelu1(float x) {
    const float c = 0.7978845608028654f;
    float t = tanhf(c * (x + 0.044715f * x * x * x));
    return 0.5f * x * (1.f + t);
}
__device__ __forceinline__ float sigmoidf(float x) { return 1.f / (1.f + expf(-x)); }

// ================= elementwise =================
__global__ void ew_gelu(const float* __restrict__ x) {
    int i = blockIdx.x * 256 + threadIdx.x;           // float4 index, grid covers NE/4
    float4 v = reinterpret_cast<const float4*>(x)[i];
    v.x = gelu1(v.x); v.y = gelu1(v.y); v.z = gelu1(v.z); v.w = gelu1(v.w);
    reinterpret_cast<float4*>(g_xg)[i] = v;
}

// reads p (gate_x pre), q (gate_a pre), v; writes a -> q, scaled_in -> p
__global__ void ew_gates(const float* __restrict__ a_param) {
    int tid = threadIdx.x;                             // column (float4) 0..255
    float4 ap = reinterpret_cast<const float4*>(a_param)[tid];
    float sp0 = log1pf(expf(ap.x));
    float sp1 = log1pf(expf(ap.y));
    float sp2 = log1pf(expf(ap.z));
    float sp3 = log1pf(expf(ap.w));
    for (int k = 0; k < 32; k++) {
        int r = blockIdx.x + k * 1024;                 // row 0..32767
        int i = r * 256 + tid;
        float4 pv = reinterpret_cast<const float4*>(g_p)[i];
        float4 qv = reinterpret_cast<const float4*>(g_q)[i];
        float4 vv = reinterpret_cast<const float4*>(g_v)[i];
        float4 ao, so;
#define GC(P,Q,V,SP,AO,SO) { \
        float gx = sigmoidf(P); float ga = sigmoidf(Q); \
        float la = -8.f * ga * (SP); float a_ = expf(la); \
        AO = a_; SO = sqrtf(fmaxf(1.f - a_*a_, 0.f)) * gx * (V); }
        GC(pv.x, qv.x, vv.x, sp0, ao.x, so.x)
        GC(pv.y, qv.y, vv.y, sp1, ao.y, so.y)
        GC(pv.z, qv.z, vv.z, sp2, ao.z, so.z)
        GC(pv.w, qv.w, vv.w, sp3, ao.w, so.w)
#undef GC
        reinterpret_cast<float4*>(g_q)[i] = ao;
        reinterpret_cast<float4*>(g_p)[i] = so;
    }
}

// ================= scans =================
// forward: h_t = a[d]*h_{t-1} + u_t  (in place on g_u)
__global__ void scan_f1(const float* __restrict__ a_fwd) {
    int d = blockIdx.x * 256 + threadIdx.x;
    int c = blockIdx.y, b = blockIdx.z;
    float a = a_fwd[d];
    int idx = (b * Sc + c * LC) * Dc + d;
    float h = 0.f;
#pragma unroll 8
    for (int t = 0; t < LC; t++) { h = fmaf(a, h, g_u[idx]); g_u[idx] = h; idx += Dc; }
    g_cV[(b * NC + c) * Dc + d] = h;
}
__global__ void scan_f2(const float* __restrict__ a_fwd) {
    int g = blockIdx.x * 256 + threadIdx.x;            // 8192 = B*D
    int b = g >> 10, d = g & 1023;
    float a = a_fwd[d];
    float aL = a;
#pragma unroll
    for (int i = 0; i < 7; i++) aL *= aL;              // a^128
    float H = 0.f;
    for (int c = 0; c < NC; c++) {
        int o = (b * NC + c) * Dc + d;
        float cv = g_cV[o];
        g_cI[o] = H;
        H = fmaf(aL, H, cv);
    }
}
__global__ void scan_f3(const float* __restrict__ a_fwd) {
    int c = blockIdx.y;
    if (c == 0) return;
    int d = blockIdx.x * 256 + threadIdx.x;
    int b = blockIdx.z;
    float a = a_fwd[d];
    float H = g_cI[(b * NC + c) * Dc + d];
    int idx = (b * Sc + c * LC) * Dc + d;
    float p = a;
#pragma unroll 8
    for (int t = 0; t < LC; t++) { g_u[idx] = fmaf(p, H, g_u[idx]); p *= a; idx += Dc; }
}

// backward (reverse): h_t = a_t*h_{t+1} + s_t   (a in g_q, s/h in g_p)
__global__ void scan_b1() {
    int d = blockIdx.x * 256 + threadIdx.x;
    int c = blockIdx.y, b = blockIdx.z;
    int idx = (b * Sc + c * LC + LC - 1) * Dc + d;
    float h = 0.f, P = 1.f;
#pragma unroll 8
    for (int t = 0; t < LC; t++) {
        float at = g_q[idx];
        h = fmaf(at, h, g_p[idx]);
        P *= at;
        g_p[idx] = h;
        idx -= Dc;
    }
    int o = (b * NC + c) * Dc + d;
    g_cV[o] = h; g_cP[o] = P;
}
__global__ void scan_b2() {
    int g = blockIdx.x * 256 + threadIdx.x;
    int b = g >> 10, d = g & 1023;
    float H = 0.f;
    for (int c = NC - 1; c >= 0; c--) {
        int o = (b * NC + c) * Dc + d;
        float cv = g_cV[o], cp = g_cP[o];
        g_cI[o] = H;
        H = fmaf(cp, H, cv);
    }
}
__global__ void scan_b3() {
    int c = blockIdx.y;
    if (c == NC - 1) return;
    int d = blockIdx.x * 256 + threadIdx.x;
    int b = blockIdx.z;
    float H = g_cI[(b * NC + c) * Dc + d];
    int idx = (b * Sc + c * LC + LC - 1) * Dc + d;
    float P = 1.f;
#pragma unroll 8
    for (int t = 0; t < LC; t++) {
        float at = g_q[idx];
        P *= at;
        g_p[idx] = fmaf(P, H, g_p[idx]);
        idx -= Dc;
    }
}

// ================= GEMM: C[M,1024] = A[M,K] @ W[K,1024] + bias (+bias2 + add) =================
#define BM 128
#define BN 128
#define BK 32
#define AST 136
#define BST 136

template <bool DUAL>
__global__ __launch_bounds__(256)
void gemm_k(const float* __restrict__ A, const float* __restrict__ A2,
            const float* __restrict__ B, const float* __restrict__ B2,
            const float* __restrict__ bias, const float* __restrict__ bias2,
            const float* __restrict__ add, float* __restrict__ C)
{
    __shared__ float As[BK][AST];   // transposed: As[k][m]
    __shared__ float Bs[BK][BST];   // Bs[k][n]
    const int tid  = threadIdx.x;
    const int lane = tid & 31;
    const int warp = tid >> 5;
    const int wm = warp & 3;        // 4 warps over M (32 rows each)
    const int wn = warp >> 2;       // 2 warps over N (64 cols each)
    const int m0 = blockIdx.y * BM;
    const int n0 = blockIdx.x * BN;
    const int KT = DUAL ? 64 : 32;

    float acc[2][8][4];
#pragma unroll
    for (int i = 0; i < 2; i++)
#pragma unroll
        for (int j = 0; j < 8; j++)
#pragma unroll
            for (int k = 0; k < 4; k++) acc[i][j][k] = 0.f;

    const int arow = tid & 127;     // A tile row
    const int akg0 = tid >> 7;      // 0..1 (k-group base)
    const int bn4  = tid & 31;      // B tile col (float4)
    const int bk0  = tid >> 5;      // 0..7 (k row base)

    float4 aReg[4], bReg[4];

    auto loadG = [&](int kt) {
        const float* Ap; const float* Bp; int koff;
        if (DUAL && kt >= 32) { Ap = A2; Bp = B2; koff = (kt - 32) * BK; }
        else                  { Ap = A;  Bp = B;  koff = kt * BK; }
#pragma unroll
        for (int r = 0; r < 4; r++) {
            int kg = akg0 + r * 2;
            aReg[r] = *reinterpret_cast<const float4*>(&Ap[(size_t)(m0 + arow) * 1024 + koff + kg * 4]);
        }
#pragma unroll
        for (int r = 0; r < 4; r++) {
            int krow = bk0 + r * 8;
            bReg[r] = *reinterpret_cast<const float4*>(&Bp[(size_t)(koff + krow) * 1024 + n0 + bn4 * 4]);
        }
    };
    auto storeS = [&]() {
#pragma unroll
        for (int r = 0; r < 4; r++) {
            int kg = akg0 + r * 2;
            As[kg * 4 + 0][arow] = tf32r(aReg[r].x);
            As[kg * 4 + 1][arow] = tf32r(aReg[r].y);
            As[kg * 4 + 2][arow] = tf32r(aReg[r].z);
            As[kg * 4 + 3][arow] = tf32r(aReg[r].w);
        }
#pragma unroll
        for (int r = 0; r < 4; r++) {
            int krow = bk0 + r * 8;
            float4 v = bReg[r];
            v.x = tf32r(v.x); v.y = tf32r(v.y); v.z = tf32r(v.z); v.w = tf32r(v.w);
            *reinterpret_cast<float4*>(&Bs[krow][bn4 * 4]) = v;
        }
    };
    auto compute = [&]() {
#pragma unroll
        for (int ks = 0; ks < 4; ks++) {
            unsigned af[2][4], bf[8][2];
            int krow  = ks * 8 + (lane & 3);
            int arow0 = wm * 32 + (lane >> 2);
#pragma unroll
            for (int mt = 0; mt < 2; mt++) {
                int r = arow0 + mt * 16;
                af[mt][0] = __float_as_uint(As[krow    ][r    ]);
                af[mt][1] = __float_as_uint(As[krow    ][r + 8]);
                af[mt][2] = __float_as_uint(As[krow + 4][r    ]);
                af[mt][3] = __float_as_uint(As[krow + 4][r + 8]);
            }
            int bcol0 = wn * 64 + (lane >> 2);
#pragma unroll
            for (int nt = 0; nt < 8; nt++) {
                int cc = bcol0 + nt * 8;
                bf[nt][0] = __float_as_uint(Bs[krow    ][cc]);
                bf[nt][1] = __float_as_uint(Bs[krow + 4][cc]);
            }
#pragma unroll
            for (int mt = 0; mt < 2; mt++)
#pragma unroll
                for (int nt = 0; nt < 8; nt++)
                    mma8(acc[mt][nt], af[mt], bf[nt]);
        }
    };

    loadG(0);
    for (int kt = 0; kt < KT; kt++) {
        __syncthreads();
        storeS();
        __syncthreads();
        if (kt + 1 < KT) loadG(kt + 1);
        compute();
    }

    // epilogue
#pragma unroll
    for (int mt = 0; mt < 2; mt++) {
        int row = m0 + wm * 32 + mt * 16 + (lane >> 2);
#pragma unroll
        for (int nt = 0; nt < 8; nt++) {
            int col = n0 + wn * 64 + nt * 8 + (lane & 3) * 2;
            float b0 = bias[col], b1 = bias[col + 1];
            if (DUAL) { b0 += bias2[col]; b1 += bias2[col + 1]; }
            size_t i0 = (size_t)row * 1024 + col;
            size_t i1 = i0 + (size_t)8 * 1024;
            float2 v0 = make_float2(acc[mt][nt][0] + b0, acc[mt][nt][1] + b1);
            float2 v1 = make_float2(acc[mt][nt][2] + b0, acc[mt][nt][3] + b1);
            if (DUAL) {
                float2 x0 = *reinterpret_cast<const float2*>(&add[i0]);
                float2 x1 = *reinterpret_cast<const float2*>(&add[i1]);
                v0.x += x0.x; v0.y += x0.y; v1.x += x1.x; v1.y += x1.y;
            }
            *reinterpret_cast<float2*>(&C[i0]) = v0;
            *reinterpret_cast<float2*>(&C[i1]) = v1;
        }
    }
}

// ================= launch =================
extern "C" void kernel_launch(void* const* d_in, const int* in_sizes, int n_in,
                              void* d_out, int out_size)
{
    const float* x       = (const float*)d_in[0];
    const float* a_fwd   = (const float*)d_in[1];
    const float* Wf1     = (const float*)d_in[2];
    const float* bf1     = (const float*)d_in[3];
    const float* Wf2     = (const float*)d_in[4];
    const float* bf2     = (const float*)d_in[5];
    const float* Wbx     = (const float*)d_in[6];
    const float* bbx     = (const float*)d_in[7];
    const float* Wgx     = (const float*)d_in[8];
    const float* bgx     = (const float*)d_in[9];
    const float* Wga     = (const float*)d_in[10];
    const float* bga     = (const float*)d_in[11];
    const float* a_param = (const float*)d_in[12];
    const float* Wb2     = (const float*)d_in[13];
    const float* bb2     = (const float*)d_in[14];
    float* out = (float*)d_out;

    float *xg, *u, *v, *p, *q;
    cudaGetSymbolAddress((void**)&xg, g_xg);
    cudaGetSymbolAddress((void**)&u,  g_u);
    cudaGetSymbolAddress((void**)&v,  g_v);
    cudaGetSymbolAddress((void**)&p,  g_p);
    cudaGetSymbolAddress((void**)&q,  g_q);

    dim3 gg(8, 256);          // N/BN x M/BM
    dim3 gs(4, NC, Bc);       // D/256 x chunks x B

    // xg = gelu(x)
    ew_gelu<<<NE / 4 / 256, 256>>>(x);
    // u = xg@Wf1+bf1 ; v = xg@Wbx+bbx
    gemm_k<false><<<gg, 256>>>(xg, nullptr, Wf1, nullptr, bf1, nullptr, nullptr, u);
    gemm_k<false><<<gg, 256>>>(xg, nullptr, Wbx, nullptr, bbx, nullptr, nullptr, v);
    // p = v@Wgx+bgx ; q = v@Wga+bga
    gemm_k<false><<<gg, 256>>>(v, nullptr, Wgx, nullptr, bgx, nullptr, nullptr, p);
    gemm_k<false><<<gg, 256>>>(v, nullptr, Wga, nullptr, bga, nullptr, nullptr, q);
    // gates: a -> q, scaled_in -> p
    ew_gates<<<1024, 256>>>(a_param);
    // forward scan (in place on u)
    scan_f1<<<gs, 256>>>(a_fwd);
    scan_f2<<<32, 256>>>(a_fwd);
    scan_f3<<<gs, 256>>>(a_fwd);
    // backward scan (in place on p, a from q)
    scan_b1<<<gs, 256>>>();
    scan_b2<<<32, 256>>>();
    scan_b3<<<gs, 256>>>();
    // out = hf@Wf2 + bf2 + hb@Wb2 + bb2 + x
    gemm_k<true><<<gg, 256>>>(u, p, Wf2, Wb2, bf2, bb2, x, out);
}

// round 4
// speedup vs baseline: 1.6865x; 1.6865x over previous
#include <cuda_runtime.h>
#include <cuda_bf16.h>
#include <cstdint>

// Problem constants
#define Bc   8
#define Sc   4096
#define Dc   1024
#define Mtot 32768            // B*S
#define NE   33554432         // Mtot*Dc elements
#define NC   32               // scan chunks
#define LC   128              // chunk length (NC*LC == Sc)

// -------- scratch (device globals: allocation-free) --------
__device__ __align__(16) float g_xg[NE];
__device__ __align__(16) float g_u [NE];   // u, then hf (in place)
__device__ __align__(16) float g_v [NE];
__device__ __align__(16) float g_p [NE];   // gate_x pre -> scaled_in -> hb (in place)
__device__ __align__(16) float g_q [NE];   // gate_a pre -> a
__device__ __align__(16) float g_Wt[6 * 1024 * 1024]; // tf32-rounded weights
__device__ float g_cV[Bc*NC*Dc];
__device__ float g_cP[Bc*NC*Dc];
__device__ float g_cI[Bc*NC*Dc];

// ================= helpers =================
__device__ __forceinline__ float tf32r(float x) {
    unsigned u; asm("cvt.rna.tf32.f32 %0, %1;" : "=r"(u) : "f"(x));
    return __uint_as_float(u);
}
__device__ __forceinline__ void mma8(float* c, const unsigned* a, const unsigned* b) {
    asm volatile(
        "mma.sync.aligned.m16n8k8.row.col.f32.tf32.tf32.f32 "
        "{%0,%1,%2,%3}, {%4,%5,%6,%7}, {%8,%9}, {%0,%1,%2,%3};\n"
        : "+f"(c[0]), "+f"(c[1]), "+f"(c[2]), "+f"(c[3])
        : "r"(a[0]), "r"(a[1]), "r"(a[2]), "r"(a[3]), "r"(b[0]), "r"(b[1]));
}
__device__ __forceinline__ float gelu1(float x) {
    const float c = 0.7978845608028654f;
    float t = tanhf(c * (x + 0.044715f * x * x * x));
    return 0.5f * x * (1.f + t);
}
__device__ __forceinline__ float sigmoidf(float x) { return 1.f / (1.f + expf(-x)); }
__device__ __forceinline__ uint32_t smem_u32(const void* p) {
    uint32_t a;
    asm("{ .reg .u64 t; cvta.to.shared.u64 t, %1; cvt.u32.u64 %0, t; }" : "=r"(a) : "l"(p));
    return a;
}
__device__ __forceinline__ void cpasync16(uint32_t sdst, const float* gsrc) {
    asm volatile("cp.async.cg.shared.global [%0], [%1], 16;\n" :: "r"(sdst), "l"(gsrc));
}

// ================= GEMM (mma.sync tf32, 3-stage cp.async pipeline) =================
// Tile: 128x128x32. 8 warps: wm(4) x wn(2), each warp 32x64 output.
// As: [m][k] stride 36 floats (144B rows; bank = (4r+k)%32 -> conflict-free frags)
// Bs: [k][n] stride 136 floats (544B rows; bank = (8k+n)%32 -> conflict-free frags)
#define AS_STR   36
#define BS_STR   136
#define A_BYTES  (128 * AS_STR * 4)     // 18432
#define B_BYTES  (32 * BS_STR * 4)      // 17408
#define SET_B    (A_BYTES + B_BYTES)    // 35840
#define SMEMSZ   (3 * SET_B)            // 107520

// TWOB: grid.x in [0,16): xb = x&7 selects N-tile, sel = x>>3 selects (B1,C1,bias1) vs (B2,C2,bias2)
// DUAL: K=2048 over (A1,B1) then (A2,B2); epilogue adds bias1+bias2+resid
template <bool TWOB, bool DUAL, bool ROUND2>
__global__ __launch_bounds__(256, 2)
void tc_gemm(const float* __restrict__ A1, const float* __restrict__ A2,
             const float* __restrict__ B1, const float* __restrict__ B2,
             const float* __restrict__ bias1, const float* __restrict__ bias2,
             const float* __restrict__ resid,
             float* __restrict__ C1, float* __restrict__ C2)
{
    constexpr int NK = DUAL ? 64 : 32;
    extern __shared__ float smem[];
    const uint32_t sb = smem_u32(smem);
    const int tid  = threadIdx.x;
    const int lane = tid & 31;
    const int warp = tid >> 5;
    const int wm = warp & 3;
    const int wn = warp >> 2;

    const int xb  = TWOB ? (blockIdx.x & 7) : blockIdx.x;
    const int sel = TWOB ? (int)(blockIdx.x >> 3) : 0;
    const int m0 = blockIdx.y * 128;
    const int n0 = xb * 128;
    const float* Bsel    = (TWOB && sel) ? B2 : B1;
    const float* biassel = (TWOB && sel) ? bias2 : bias1;
    float*       Csel    = (TWOB && sel) ? C2 : C1;

    float acc[2][8][4];
#pragma unroll
    for (int i = 0; i < 2; i++)
#pragma unroll
        for (int j = 0; j < 8; j++)
#pragma unroll
            for (int k = 0; k < 4; k++) acc[i][j][k] = 0.f;

    // ---- async tile issue ----
    auto issue = [&](int c) {
        const int slot = c % 3;
        const float* Ap; const float* Bp; int koff;
        if (DUAL && c >= 32) { Ap = A2; Bp = B2;   koff = (c - 32) * 32; }
        else                 { Ap = A1; Bp = Bsel; koff = c * 32; }
        const uint32_t sa = sb + slot * SET_B;
        const uint32_t sB = sa + A_BYTES;
#pragma unroll
        for (int i = 0; i < 4; i++) {
            int id = tid + i * 256;
            int r = id >> 3, kq = id & 7;
            cpasync16(sa + (uint32_t)(r * 144 + kq * 16),
                      Ap + (size_t)(m0 + r) * 1024 + koff + kq * 4);
        }
#pragma unroll
        for (int i = 0; i < 4; i++) {
            int id = tid + i * 256;
            int kr = id >> 5, nc = id & 31;
            cpasync16(sB + (uint32_t)(kr * 544 + nc * 16),
                      Bp + (size_t)(koff + kr) * 1024 + n0 + nc * 4);
        }
        asm volatile("cp.async.commit_group;\n");
    };

    auto compute = [&](int slot) {
        const float* As = smem + slot * (SET_B / 4);
        const float* Bs = As + (A_BYTES / 4);
        const int r0    = wm * 32 + (lane >> 2);
        const int bcol0 = wn * 64 + (lane >> 2);
#pragma unroll
        for (int ks = 0; ks < 4; ks++) {
            const int krow = ks * 8 + (lane & 3);
            unsigned af[2][4], bf[8][2];
#pragma unroll
            for (int mt = 0; mt < 2; mt++) {
                int r = r0 + mt * 16;
                af[mt][0] = __float_as_uint(As[r * AS_STR + krow]);
                af[mt][1] = __float_as_uint(As[(r + 8) * AS_STR + krow]);
                af[mt][2] = __float_as_uint(As[r * AS_STR + krow + 4]);
                af[mt][3] = __float_as_uint(As[(r + 8) * AS_STR + krow + 4]);
            }
#pragma unroll
            for (int nt = 0; nt < 8; nt++) {
                int cc = bcol0 + nt * 8;
                bf[nt][0] = __float_as_uint(Bs[krow * BS_STR + cc]);
                bf[nt][1] = __float_as_uint(Bs[(krow + 4) * BS_STR + cc]);
            }
#pragma unroll
            for (int mt = 0; mt < 2; mt++)
#pragma unroll
                for (int nt = 0; nt < 8; nt++)
                    mma8(acc[mt][nt], af[mt], bf[nt]);
        }
    };

    // prologue: 2 stages in flight
    issue(0);
    issue(1);
    for (int k = 0; k < NK; k++) {
        if (k < NK - 1) asm volatile("cp.async.wait_group 1;\n");
        else            asm volatile("cp.async.wait_group 0;\n");
        __syncthreads();
        if (k + 2 < NK) issue(k + 2);
        compute(k % 3);
    }

    // ---- epilogue ----
#pragma unroll
    for (int mt = 0; mt < 2; mt++) {
        int row = m0 + wm * 32 + mt * 16 + (lane >> 2);
#pragma unroll
        for (int nt = 0; nt < 8; nt++) {
            int col = n0 + wn * 64 + nt * 8 + (lane & 3) * 2;
            float b0 = biassel[col], b1 = biassel[col + 1];
            if (DUAL) { b0 += bias2[col]; b1 += bias2[col + 1]; }
            size_t i0 = (size_t)row * 1024 + col;
            size_t i1 = i0 + (size_t)8 * 1024;
            float2 v0 = make_float2(acc[mt][nt][0] + b0, acc[mt][nt][1] + b1);
            float2 v1 = make_float2(acc[mt][nt][2] + b0, acc[mt][nt][3] + b1);
            if (DUAL) {
                float2 x0 = *reinterpret_cast<const float2*>(&resid[i0]);
                float2 x1 = *reinterpret_cast<const float2*>(&resid[i1]);
                v0.x += x0.x; v0.y += x0.y; v1.x += x1.x; v1.y += x1.y;
            }
            if (ROUND2 && sel) {
                v0.x = tf32r(v0.x); v0.y = tf32r(v0.y);
                v1.x = tf32r(v1.x); v1.y = tf32r(v1.y);
            }
            *reinterpret_cast<float2*>(&Csel[i0]) = v0;
            *reinterpret_cast<float2*>(&Csel[i1]) = v1;
        }
    }
}

// ================= weight tf32 round (no transpose; Bs uses native [K,N]) =================
__global__ void wround(const float* __restrict__ w0, const float* __restrict__ w1,
                       const float* __restrict__ w2, const float* __restrict__ w3,
                       const float* __restrict__ w4, const float* __restrict__ w5)
{
    const float* srcs[6] = {w0, w1, w2, w3, w4, w5};
    const float* src = srcs[blockIdx.y];
    float* dst = g_Wt + (size_t)blockIdx.y * 1048576;
    int i = blockIdx.x * 256 + threadIdx.x;             // float4 idx, 262144 per weight
    float4 v = reinterpret_cast<const float4*>(src)[i];
    v.x = tf32r(v.x); v.y = tf32r(v.y); v.z = tf32r(v.z); v.w = tf32r(v.w);
    reinterpret_cast<float4*>(dst)[i] = v;
}

// ================= elementwise =================
__global__ void ew_gelu(const float* __restrict__ x) {
    int i = blockIdx.x * 256 + threadIdx.x;
    float4 v = reinterpret_cast<const float4*>(x)[i];
    v.x = tf32r(gelu1(v.x)); v.y = tf32r(gelu1(v.y));
    v.z = tf32r(gelu1(v.z)); v.w = tf32r(gelu1(v.w));
    reinterpret_cast<float4*>(g_xg)[i] = v;
}

// reads p (gate_x pre), q (gate_a pre), v; writes a -> q, scaled_in -> p
__global__ void ew_gates(const float* __restrict__ a_param) {
    int tid = threadIdx.x;
    float4 ap = reinterpret_cast<const float4*>(a_param)[tid];
    float sp0 = log1pf(expf(ap.x));
    float sp1 = log1pf(expf(ap.y));
    float sp2 = log1pf(expf(ap.z));
    float sp3 = log1pf(expf(ap.w));
    for (int k = 0; k < 32; k++) {
        int r = blockIdx.x + k * 1024;
        int i = r * 256 + tid;
        float4 pv = reinterpret_cast<const float4*>(g_p)[i];
        float4 qv = reinterpret_cast<const float4*>(g_q)[i];
        float4 vv = reinterpret_cast<const float4*>(g_v)[i];
        float4 ao, so;
#define GC(P,Q,V,SP,AO,SO) { \
        float gx = sigmoidf(P); float ga = sigmoidf(Q); \
        float la = -8.f * ga * (SP); float a_ = expf(la); \
        AO = a_; SO = sqrtf(fmaxf(1.f - a_*a_, 0.f)) * gx * (V); }
        GC(pv.x, qv.x, vv.x, sp0, ao.x, so.x)
        GC(pv.y, qv.y, vv.y, sp1, ao.y, so.y)
        GC(pv.z, qv.z, vv.z, sp2, ao.z, so.z)
        GC(pv.w, qv.w, vv.w, sp3, ao.w, so.w)
#undef GC
        reinterpret_cast<float4*>(g_q)[i] = ao;
        reinterpret_cast<float4*>(g_p)[i] = so;
    }
}

// ================= scans =================
__global__ void scan_f1(const float* __restrict__ a_fwd) {
    int d = blockIdx.x * 256 + threadIdx.x;
    int c = blockIdx.y, b = blockIdx.z;
    float a = a_fwd[d];
    int idx = (b * Sc + c * LC) * Dc + d;
    float h = 0.f;
#pragma unroll 8
    for (int t = 0; t < LC; t++) { h = fmaf(a, h, g_u[idx]); g_u[idx] = tf32r(h); idx += Dc; }
    g_cV[(b * NC + c) * Dc + d] = h;
}
__global__ void scan_f2(const float* __restrict__ a_fwd) {
    int g = blockIdx.x * 256 + threadIdx.x;
    int b = g >> 10, d = g & 1023;
    float a = a_fwd[d];
    float aL = a;
#pragma unroll
    for (int i = 0; i < 7; i++) aL *= aL;
    float H = 0.f;
    for (int c = 0; c < NC; c++) {
        int o = (b * NC + c) * Dc + d;
        float cv = g_cV[o];
        g_cI[o] = H;
        H = fmaf(aL, H, cv);
    }
}
__global__ void scan_f3(const float* __restrict__ a_fwd) {
    int c = blockIdx.y;
    if (c == 0) return;
    int d = blockIdx.x * 256 + threadIdx.x;
    int b = blockIdx.z;
    float a = a_fwd[d];
    float H = g_cI[(b * NC + c) * Dc + d];
    int idx = (b * Sc + c * LC) * Dc + d;
    float p = a;
#pragma unroll 8
    for (int t = 0; t < LC; t++) { g_u[idx] = tf32r(fmaf(p, H, g_u[idx])); p *= a; idx += Dc; }
}
__global__ void scan_b1() {
    int d = blockIdx.x * 256 + threadIdx.x;
    int c = blockIdx.y, b = blockIdx.z;
    int idx = (b * Sc + c * LC + LC - 1) * Dc + d;
    float h = 0.f, P = 1.f;
#pragma unroll 8
    for (int t = 0; t < LC; t++) {
        float at = g_q[idx];
        h = fmaf(at, h, g_p[idx]);
        P *= at;
        g_p[idx] = tf32r(h);
        idx -= Dc;
    }
    int o = (b * NC + c) * Dc + d;
    g_cV[o] = h; g_cP[o] = P;
}
__global__ void scan_b2() {
    int g = blockIdx.x * 256 + threadIdx.x;
    int b = g >> 10, d = g & 1023;
    float H = 0.f;
    for (int c = NC - 1; c >= 0; c--) {
        int o = (b * NC + c) * Dc + d;
        float cv = g_cV[o], cp = g_cP[o];
        g_cI[o] = H;
        H = fmaf(cp, H, cv);
    }
}
__global__ void scan_b3() {
    int c = blockIdx.y;
    if (c == NC - 1) return;
    int d = blockIdx.x * 256 + threadIdx.x;
    int b = blockIdx.z;
    float H = g_cI[(b * NC + c) * Dc + d];
    int idx = (b * Sc + c * LC + LC - 1) * Dc + d;
    float P = 1.f;
#pragma unroll 8
    for (int t = 0; t < LC; t++) {
        float at = g_q[idx];
        P *= at;
        g_p[idx] = tf32r(fmaf(P, H, g_p[idx]));
        idx -= Dc;
    }
}

// ================= launch =================
extern "C" void kernel_launch(void* const* d_in, const int* in_sizes, int n_in,
                              void* d_out, int out_size)
{
    const float* x       = (const float*)d_in[0];
    const float* a_fwd   = (const float*)d_in[1];
    const float* Wf1     = (const float*)d_in[2];
    const float* bf1     = (const float*)d_in[3];
    const float* Wf2     = (const float*)d_in[4];
    const float* bf2     = (const float*)d_in[5];
    const float* Wbx     = (const float*)d_in[6];
    const float* bbx     = (const float*)d_in[7];
    const float* Wgx     = (const float*)d_in[8];
    const float* bgx     = (const float*)d_in[9];
    const float* Wga     = (const float*)d_in[10];
    const float* bga     = (const float*)d_in[11];
    const float* a_param = (const float*)d_in[12];
    const float* Wb2     = (const float*)d_in[13];
    const float* bb2     = (const float*)d_in[14];
    float* out = (float*)d_out;

    float *xg, *u, *v, *p, *q, *wt;
    cudaGetSymbolAddress((void**)&xg, g_xg);
    cudaGetSymbolAddress((void**)&u,  g_u);
    cudaGetSymbolAddress((void**)&v,  g_v);
    cudaGetSymbolAddress((void**)&p,  g_p);
    cudaGetSymbolAddress((void**)&q,  g_q);
    cudaGetSymbolAddress((void**)&wt, g_Wt);
    const float* Wr_f1 = wt + 0u * 1048576;
    const float* Wr_bx = wt + 1u * 1048576;
    const float* Wr_gx = wt + 2u * 1048576;
    const float* Wr_ga = wt + 3u * 1048576;
    const float* Wr_f2 = wt + 4u * 1048576;
    const float* Wr_b2 = wt + 5u * 1048576;

    cudaFuncSetAttribute(tc_gemm<true,  false, true>,  cudaFuncAttributeMaxDynamicSharedMemorySize, SMEMSZ);
    cudaFuncSetAttribute(tc_gemm<true,  false, false>, cudaFuncAttributeMaxDynamicSharedMemorySize, SMEMSZ);
    cudaFuncSetAttribute(tc_gemm<false, true,  false>, cudaFuncAttributeMaxDynamicSharedMemorySize, SMEMSZ);

    dim3 gp(16, 256);         // pair: 2x N-tiles x M-tiles
    dim3 gf(8, 256);          // final
    dim3 gs(4, NC, Bc);       // D/256 x chunks x B

    // round weights to tf32
    wround<<<dim3(1024, 6), 256>>>(Wf1, Wbx, Wgx, Wga, Wf2, Wb2);
    // xg = tf32(gelu(x))
    ew_gelu<<<NE / 4 / 256, 256>>>(x);
    // u = xg@Wf1+bf1 ; v = tf32(xg@Wbx+bbx)
    tc_gemm<true, false, true><<<gp, 256, SMEMSZ>>>(xg, nullptr, Wr_f1, Wr_bx, bf1, bbx, nullptr, u, v);
    // p = v@Wgx+bgx ; q = v@Wga+bga
    tc_gemm<true, false, false><<<gp, 256, SMEMSZ>>>(v, nullptr, Wr_gx, Wr_ga, bgx, bga, nullptr, p, q);
    // gates: a -> q, scaled_in -> p
    ew_gates<<<1024, 256>>>(a_param);
    // forward scan (in place on u)
    scan_f1<<<gs, 256>>>(a_fwd);
    scan_f2<<<32, 256>>>(a_fwd);
    scan_f3<<<gs, 256>>>(a_fwd);
    // backward scan (in place on p, a from q)
    scan_b1<<<gs, 256>>>();
    scan_b2<<<32, 256>>>();
    scan_b3<<<gs, 256>>>();
    // out = hf@Wf2 + hb@Wb2 + bf2 + bb2 + x
    tc_gemm<false, true, false><<<gf, 256, SMEMSZ>>>(u, p, Wr_f2, Wr_b2, bf2, bb2, x, out, nullptr);
}

// round 5
// speedup vs baseline: 1.7411x; 1.0324x over previous
#include <cuda_runtime.h>
#include <cuda_bf16.h>
#include <cstdint>

// Problem constants
#define Bc   8
#define Sc   4096
#define Dc   1024
#define Mtot 32768            // B*S
#define NE   33554432         // Mtot*Dc elements
#define NC   32               // scan chunks
#define LC   128              // chunk length (NC*LC == Sc)

// -------- scratch (device globals: allocation-free) --------
__device__ __align__(16) float g_xg[NE];
__device__ __align__(16) float g_u [NE];   // u, then hf (in place)
__device__ __align__(16) float g_v [NE];
__device__ __align__(16) float g_p [NE];   // gate_x pre -> hb (in place)
__device__ __align__(16) float g_q [NE];   // gate_a pre -> a
__device__ __align__(16) float g_Wt[6 * 1024 * 1024]; // pair-interleaved tf32 weights
__device__ float g_cV[Bc*NC*Dc];
__device__ float g_cP[Bc*NC*Dc];
__device__ float g_cI[Bc*NC*Dc];

// ================= helpers =================
__device__ __forceinline__ float tf32r(float x) {
    unsigned u; asm("cvt.rna.tf32.f32 %0, %1;" : "=r"(u) : "f"(x));
    return __uint_as_float(u);
}
__device__ __forceinline__ void mma8(float* c, const unsigned* a, const unsigned* b) {
    asm volatile(
        "mma.sync.aligned.m16n8k8.row.col.f32.tf32.tf32.f32 "
        "{%0,%1,%2,%3}, {%4,%5,%6,%7}, {%8,%9}, {%0,%1,%2,%3};\n"
        : "+f"(c[0]), "+f"(c[1]), "+f"(c[2]), "+f"(c[3])
        : "r"(a[0]), "r"(a[1]), "r"(a[2]), "r"(a[3]), "r"(b[0]), "r"(b[1]));
}
__device__ __forceinline__ float gelu1(float x) {
    const float c = 0.7978845608028654f;
    float t = tanhf(c * (x + 0.044715f * x * x * x));
    return 0.5f * x * (1.f + t);
}
__device__ __forceinline__ float sigmoidf(float x) { return 1.f / (1.f + expf(-x)); }
__device__ __forceinline__ uint32_t smem_u32(const void* p) {
    uint32_t a;
    asm("{ .reg .u64 t; cvta.to.shared.u64 t, %1; cvt.u32.u64 %0, t; }" : "=r"(a) : "l"(p));
    return a;
}
__device__ __forceinline__ void cpasync16(uint32_t sdst, const float* gsrc) {
    asm volatile("cp.async.cg.shared.global [%0], [%1], 16;\n" :: "r"(sdst), "l"(gsrc));
}

// ================= GEMM (mma.sync tf32, 3-stage cp.async, LDS.64 B frags) ========
// Tile 128x128x32. 8 warps: wm(4) x wn(2), warp tile 32x64.
// As: [m][k] stride 36 floats (144B rows) -> conflict-free LDS.32 frags.
// Bs: pair-interleaved: 16 rows (ksj = ks*4+j), each row 128 float2 pairs
//     (B[k][n], B[k+4][n]) with k = ks*8 + j.  word8(ksj,cc) = ksj*136 + (cc ^ (4*(ksj&3))).
//     Row stride 136 words8 = 1088B. LDS.64 reads verified conflict-free.
#define AS_STR   36
#define A_BYTES  (128 * AS_STR * 4)     // 18432
#define B_BYTES  (16 * 136 * 8)        // 17408
#define SET_B    (A_BYTES + B_BYTES)    // 35840
#define SMEMSZ   (3 * SET_B)            // 107520

// TWOB: grid.x in [0,16): xb = x&7 N-tile, sel = x>>3 picks (B1,C1,bias1)/(B2,C2,bias2)
// DUAL: K=2048 over (A1,B1) then (A2,B2); epilogue adds bias1+bias2+resid
template <bool TWOB, bool DUAL, bool ROUND2>
__global__ __launch_bounds__(256, 2)
void tc_gemm(const float* __restrict__ A1, const float* __restrict__ A2,
             const float* __restrict__ B1, const float* __restrict__ B2,
             const float* __restrict__ bias1, const float* __restrict__ bias2,
             const float* __restrict__ resid,
             float* __restrict__ C1, float* __restrict__ C2)
{
    constexpr int NK = DUAL ? 64 : 32;
    extern __shared__ float smem[];
    const uint32_t sb = smem_u32(smem);
    const int tid  = threadIdx.x;
    const int lane = tid & 31;
    const int warp = tid >> 5;
    const int wm = warp & 3;
    const int wn = warp >> 2;

    const int xb  = TWOB ? (blockIdx.x & 7) : blockIdx.x;
    const int sel = TWOB ? (int)(blockIdx.x >> 3) : 0;
    const int m0 = blockIdx.y * 128;
    const int n0 = xb * 128;
    const float* Bsel    = (TWOB && sel) ? B2 : B1;
    const float* biassel = (TWOB && sel) ? bias2 : bias1;
    float*       Csel    = (TWOB && sel) ? C2 : C1;

    float acc[2][8][4];
#pragma unroll
    for (int i = 0; i < 2; i++)
#pragma unroll
        for (int j = 0; j < 8; j++)
#pragma unroll
            for (int k = 0; k < 4; k++) acc[i][j][k] = 0.f;

    // ---- async tile issue ----
    auto issue = [&](int c) {
        const int slot = c % 3;
        const float* Ap; const float* Bp; int cl;
        if (DUAL && c >= 32) { Ap = A2; Bp = B2;   cl = c - 32; }
        else                 { Ap = A1; Bp = Bsel; cl = c; }
        const int koff = cl * 32;
        const uint32_t sa = sb + slot * SET_B;
        const uint32_t sB = sa + A_BYTES;
        // A: row-major 144B-stride rows
#pragma unroll
        for (int i = 0; i < 4; i++) {
            int id = tid + i * 256;
            int r = id >> 3, kq = id & 7;
            cpasync16(sa + (uint32_t)(r * 144 + kq * 16),
                      Ap + (size_t)(m0 + r) * 1024 + koff + kq * 4);
        }
        // B: pair-interleaved global -> swizzled smem rows
        // global Bi[kgj][n][e], kgj = cl*16 + ksj, chunk ch covers n = 2ch,2ch+1
#pragma unroll
        for (int i = 0; i < 4; i++) {
            int id = tid + i * 256;
            int ksj = id >> 6, ch = id & 63;
            uint32_t w8 = (uint32_t)(ksj * 136 + ((2 * ch) ^ ((ksj & 3) << 2)));
            // n0 shifts chunk index by n0/2 (n0 multiple of 128 -> swizzle bits 2-3 unaffected? n0/2=64: bits>=6; XOR mask is bits 2-3 of chunk... chunk+64 keeps low bits)
            cpasync16(sB + w8 * 8,
                      Bp + (size_t)(cl * 16 + ksj) * 2048 + (size_t)n0 * 2 + ch * 4);
        }
        asm volatile("cp.async.commit_group;\n");
    };

    auto compute = [&](int slot) {
        const float* As = smem + slot * (SET_B / 4);
        const float* Bs = As + (A_BYTES / 4);
        const int r0  = wm * 32 + (lane >> 2);
        const int klB = lane & 3;
        const int q   = lane >> 2;
        const int ccb = wn * 64 + q;
#pragma unroll
        for (int ks = 0; ks < 4; ks++) {
            const int krow = ks * 8 + klB;
            unsigned af[2][4], bf[8][2];
#pragma unroll
            for (int mt = 0; mt < 2; mt++) {
                int r = r0 + mt * 16;
                af[mt][0] = __float_as_uint(As[r * AS_STR + krow]);
                af[mt][1] = __float_as_uint(As[(r + 8) * AS_STR + krow]);
                af[mt][2] = __float_as_uint(As[r * AS_STR + krow + 4]);
                af[mt][3] = __float_as_uint(As[(r + 8) * AS_STR + krow + 4]);
            }
            const int rowb = (ks * 4 + klB) * 136;
#pragma unroll
            for (int nt = 0; nt < 8; nt++) {
                int cc = ccb + nt * 8;
                int w8 = rowb + (cc ^ (klB << 2));
                float2 bv = *reinterpret_cast<const float2*>(Bs + w8 * 2);
                bf[nt][0] = __float_as_uint(bv.x);
                bf[nt][1] = __float_as_uint(bv.y);
            }
#pragma unroll
            for (int mt = 0; mt < 2; mt++)
#pragma unroll
                for (int nt = 0; nt < 8; nt++)
                    mma8(acc[mt][nt], af[mt], bf[nt]);
        }
    };

    issue(0);
    issue(1);
    for (int k = 0; k < NK; k++) {
        if (k < NK - 1) asm volatile("cp.async.wait_group 1;\n");
        else            asm volatile("cp.async.wait_group 0;\n");
        __syncthreads();
        if (k + 2 < NK) issue(k + 2);
        compute(k % 3);
    }

    // ---- epilogue ----
#pragma unroll
    for (int mt = 0; mt < 2; mt++) {
        int row = m0 + wm * 32 + mt * 16 + (lane >> 2);
#pragma unroll
        for (int nt = 0; nt < 8; nt++) {
            int col = n0 + wn * 64 + nt * 8 + (lane & 3) * 2;
            float b0 = biassel[col], b1 = biassel[col + 1];
            if (DUAL) { b0 += bias2[col]; b1 += bias2[col + 1]; }
            size_t i0 = (size_t)row * 1024 + col;
            size_t i1 = i0 + (size_t)8 * 1024;
            float2 v0 = make_float2(acc[mt][nt][0] + b0, acc[mt][nt][1] + b1);
            float2 v1 = make_float2(acc[mt][nt][2] + b0, acc[mt][nt][3] + b1);
            if (DUAL) {
                float2 x0 = *reinterpret_cast<const float2*>(&resid[i0]);
                float2 x1 = *reinterpret_cast<const float2*>(&resid[i1]);
                v0.x += x0.x; v0.y += x0.y; v1.x += x1.x; v1.y += x1.y;
            }
            if (ROUND2 && sel) {
                v0.x = tf32r(v0.x); v0.y = tf32r(v0.y);
                v1.x = tf32r(v1.x); v1.y = tf32r(v1.y);
            }
            *reinterpret_cast<float2*>(&Csel[i0]) = v0;
            *reinterpret_cast<float2*>(&Csel[i1]) = v1;
        }
    }
}

// ================= weight pair-interleave + tf32 round =================
// Bi[kgj][n][e] = tf32(W[(kgj>>2)*8 + (kgj&3) + 4e][n]),  kgj in [0,512), n in [0,1024), e in {0,1}
__global__ void wintl(const float* __restrict__ w0, const float* __restrict__ w1,
                      const float* __restrict__ w2, const float* __restrict__ w3,
                      const float* __restrict__ w4, const float* __restrict__ w5)
{
    const float* srcs[6] = {w0, w1, w2, w3, w4, w5};
    const float* src = srcs[blockIdx.y];
    float* dst = g_Wt + (size_t)blockIdx.y * 1048576;
    const int kg = blockIdx.x;          // 0..127
    const int t = threadIdx.x;          // 0..255
#pragma unroll
    for (int j = 0; j < 4; j++) {
#pragma unroll
        for (int nn = 0; nn < 4; nn++) {
            int n = nn * 256 + t;
            float lo = src[(size_t)(kg * 8 + j) * 1024 + n];
            float hi = src[(size_t)(kg * 8 + j + 4) * 1024 + n];
            float2 o = make_float2(tf32r(lo), tf32r(hi));
            *reinterpret_cast<float2*>(&dst[((size_t)(kg * 4 + j) * 1024 + n) * 2]) = o;
        }
    }
}

// ================= elementwise =================
__global__ void ew_gelu(const float* __restrict__ x) {
    int i = blockIdx.x * 256 + threadIdx.x;
    float4 v = reinterpret_cast<const float4*>(x)[i];
    v.x = tf32r(gelu1(v.x)); v.y = tf32r(gelu1(v.y));
    v.z = tf32r(gelu1(v.z)); v.w = tf32r(gelu1(v.w));
    reinterpret_cast<float4*>(g_xg)[i] = v;
}

// ================= scans =================
__global__ void scan_f1(const float* __restrict__ a_fwd) {
    int d = blockIdx.x * 256 + threadIdx.x;
    int c = blockIdx.y, b = blockIdx.z;
    float a = a_fwd[d];
    int idx = (b * Sc + c * LC) * Dc + d;
    float h = 0.f;
#pragma unroll 8
    for (int t = 0; t < LC; t++) { h = fmaf(a, h, g_u[idx]); g_u[idx] = tf32r(h); idx += Dc; }
    g_cV[(b * NC + c) * Dc + d] = h;
}
__global__ void scan_f2(const float* __restrict__ a_fwd) {
    int g = blockIdx.x * 256 + threadIdx.x;
    int b = g >> 10, d = g & 1023;
    float a = a_fwd[d];
    float aL = a;
#pragma unroll
    for (int i = 0; i < 7; i++) aL *= aL;
    float H = 0.f;
    for (int c = 0; c < NC; c++) {
        int o = (b * NC + c) * Dc + d;
        float cv = g_cV[o];
        g_cI[o] = H;
        H = fmaf(aL, H, cv);
    }
}
__global__ void scan_f3(const float* __restrict__ a_fwd) {
    int c = blockIdx.y;
    if (c == 0) return;
    int d = blockIdx.x * 256 + threadIdx.x;
    int b = blockIdx.z;
    float a = a_fwd[d];
    float H = g_cI[(b * NC + c) * Dc + d];
    int idx = (b * Sc + c * LC) * Dc + d;
    float p = a;
#pragma unroll 8
    for (int t = 0; t < LC; t++) { g_u[idx] = tf32r(fmaf(p, H, g_u[idx])); p *= a; idx += Dc; }
}
// fused gates + reverse local scan:
// reads p(gate_x pre), q(gate_a pre), v; writes a -> q, h -> p, carries -> cV/cP
__global__ void scan_b1(const float* __restrict__ a_param) {
    int d = blockIdx.x * 256 + threadIdx.x;
    int c = blockIdx.y, b = blockIdx.z;
    float sp = log1pf(expf(a_param[d]));
    int idx = (b * Sc + c * LC + LC - 1) * Dc + d;
    float h = 0.f, P = 1.f;
#pragma unroll 4
    for (int t = 0; t < LC; t++) {
        float pv = g_p[idx], qv = g_q[idx], vv = g_v[idx];
        float gx = sigmoidf(pv);
        float ga = sigmoidf(qv);
        float a  = expf(-8.f * ga * sp);
        float si = sqrtf(fmaxf(1.f - a * a, 0.f)) * gx * vv;
        h = fmaf(a, h, si);
        P *= a;
        g_q[idx] = a;
        g_p[idx] = tf32r(h);
        idx -= Dc;
    }
    int o = (b * NC + c) * Dc + d;
    g_cV[o] = h; g_cP[o] = P;
}
__global__ void scan_b2() {
    int g = blockIdx.x * 256 + threadIdx.x;
    int b = g >> 10, d = g & 1023;
    float H = 0.f;
    for (int c = NC - 1; c >= 0; c--) {
        int o = (b * NC + c) * Dc + d;
        float cv = g_cV[o], cp = g_cP[o];
        g_cI[o] = H;
        H = fmaf(cp, H, cv);
    }
}
__global__ void scan_b3() {
    int c = blockIdx.y;
    if (c == NC - 1) return;
    int d = blockIdx.x * 256 + threadIdx.x;
    int b = blockIdx.z;
    float H = g_cI[(b * NC + c) * Dc + d];
    int idx = (b * Sc + c * LC + LC - 1) * Dc + d;
    float P = 1.f;
#pragma unroll 8
    for (int t = 0; t < LC; t++) {
        float at = g_q[idx];
        P *= at;
        g_p[idx] = tf32r(fmaf(P, H, g_p[idx]));
        idx -= Dc;
    }
}

// ================= launch =================
extern "C" void kernel_launch(void* const* d_in, const int* in_sizes, int n_in,
                              void* d_out, int out_size)
{
    const float* x       = (const float*)d_in[0];
    const float* a_fwd   = (const float*)d_in[1];
    const float* Wf1     = (const float*)d_in[2];
    const float* bf1     = (const float*)d_in[3];
    const float* Wf2     = (const float*)d_in[4];
    const float* bf2     = (const float*)d_in[5];
    const float* Wbx     = (const float*)d_in[6];
    const float* bbx     = (const float*)d_in[7];
    const float* Wgx     = (const float*)d_in[8];
    const float* bgx     = (const float*)d_in[9];
    const float* Wga     = (const float*)d_in[10];
    const float* bga     = (const float*)d_in[11];
    const float* a_param = (const float*)d_in[12];
    const float* Wb2     = (const float*)d_in[13];
    const float* bb2     = (const float*)d_in[14];
    float* out = (float*)d_out;

    float *xg, *u, *v, *p, *q, *wt;
    cudaGetSymbolAddress((void**)&xg, g_xg);
    cudaGetSymbolAddress((void**)&u,  g_u);
    cudaGetSymbolAddress((void**)&v,  g_v);
    cudaGetSymbolAddress((void**)&p,  g_p);
    cudaGetSymbolAddress((void**)&q,  g_q);
    cudaGetSymbolAddress((void**)&wt, g_Wt);
    const float* Wr_f1 = wt + 0u * 1048576;
    const float* Wr_bx = wt + 1u * 1048576;
    const float* Wr_gx = wt + 2u * 1048576;
    const float* Wr_ga = wt + 3u * 1048576;
    const float* Wr_f2 = wt + 4u * 1048576;
    const float* Wr_b2 = wt + 5u * 1048576;

    cudaFuncSetAttribute(tc_gemm<true,  false, true>,  cudaFuncAttributeMaxDynamicSharedMemorySize, SMEMSZ);
    cudaFuncSetAttribute(tc_gemm<true,  false, false>, cudaFuncAttributeMaxDynamicSharedMemorySize, SMEMSZ);
    cudaFuncSetAttribute(tc_gemm<false, true,  false>, cudaFuncAttributeMaxDynamicSharedMemorySize, SMEMSZ);

    dim3 gp(16, 256);         // pair: 2x N-tiles x M-tiles
    dim3 gf(8, 256);          // final
    dim3 gs(4, NC, Bc);       // D/256 x chunks x B

    // pair-interleave + round weights
    wintl<<<dim3(128, 6), 256>>>(Wf1, Wbx, Wgx, Wga, Wf2, Wb2);
    // xg = tf32(gelu(x))
    ew_gelu<<<NE / 4 / 256, 256>>>(x);
    // u = xg@Wf1+bf1 ; v = tf32(xg@Wbx+bbx)
    tc_gemm<true, false, true><<<gp, 256, SMEMSZ>>>(xg, nullptr, Wr_f1, Wr_bx, bf1, bbx, nullptr, u, v);
    // p = v@Wgx+bgx ; q = v@Wga+bga
    tc_gemm<true, false, false><<<gp, 256, SMEMSZ>>>(v, nullptr, Wr_gx, Wr_ga, bgx, bga, nullptr, p, q);
    // forward scan (in place on u)
    scan_f1<<<gs, 256>>>(a_fwd);
    scan_f2<<<32, 256>>>(a_fwd);
    scan_f3<<<gs, 256>>>(a_fwd);
    // backward: fused gates + local scan, then carries + correction
    scan_b1<<<gs, 256>>>(a_param);
    scan_b2<<<32, 256>>>();
    scan_b3<<<gs, 256>>>();
    // out = hf@Wf2 + hb@Wb2 + bf2 + bb2 + x
    tc_gemm<false, true, false><<<gf, 256, SMEMSZ>>>(u, p, Wr_f2, Wr_b2, bf2, bb2, x, out, nullptr);
}

// round 8
// speedup vs baseline: 1.8033x; 1.0357x over previous
#include <cuda_runtime.h>
#include <cuda_bf16.h>
#include <cstdint>

// Problem constants
#define Bc   8
#define Sc   4096
#define Dc   1024
#define Mtot 32768            // B*S
#define NE   33554432         // Mtot*Dc elements
#define NC   32               // scan chunks
#define LC   128              // chunk length (NC*LC == Sc)

// -------- scratch (device globals: allocation-free) --------
__device__ __align__(16) float g_xg[NE];
__device__ __align__(16) float g_u [NE];   // u, then hf (in place)
__device__ __align__(16) float g_v [NE];
__device__ __align__(16) float g_p [NE];   // gate_x pre -> hb (in place)
__device__ __align__(16) float g_q [NE];   // gate_a pre -> a
__device__ __align__(16) float g_Wt[6 * 1024 * 1024]; // pair-interleaved tf32 weights
__device__ __align__(16) float g_cV [Bc*NC*Dc];   // fwd carries
__device__ __align__(16) float g_cI [Bc*NC*Dc];   // fwd prefixes
__device__ __align__(16) float g_cVb[Bc*NC*Dc];   // bwd carries
__device__ __align__(16) float g_cP [Bc*NC*Dc];   // bwd chunk products
__device__ __align__(16) float g_cIb[Bc*NC*Dc];   // bwd prefixes

// ================= helpers =================
__device__ __forceinline__ float tf32r(float x) {
    unsigned u; asm("cvt.rna.tf32.f32 %0, %1;" : "=r"(u) : "f"(x));
    return __uint_as_float(u);
}
__device__ __forceinline__ void mma8(float* c, const unsigned* a, const unsigned* b) {
    asm volatile(
        "mma.sync.aligned.m16n8k8.row.col.f32.tf32.tf32.f32 "
        "{%0,%1,%2,%3}, {%4,%5,%6,%7}, {%8,%9}, {%0,%1,%2,%3};\n"
        : "+f"(c[0]), "+f"(c[1]), "+f"(c[2]), "+f"(c[3])
        : "r"(a[0]), "r"(a[1]), "r"(a[2]), "r"(a[3]), "r"(b[0]), "r"(b[1]));
}
__device__ __forceinline__ float gelu1(float x) {
    const float c = 0.7978845608028654f;
    float t = tanhf(c * (x + 0.044715f * x * x * x));
    return 0.5f * x * (1.f + t);
}
__device__ __forceinline__ float sigmoidf(float x) { return 1.f / (1.f + expf(-x)); }
__device__ __forceinline__ uint32_t smem_u32(const void* p) {
    uint32_t a;
    asm("{ .reg .u64 t; cvta.to.shared.u64 t, %1; cvt.u32.u64 %0, t; }" : "=r"(a) : "l"(p));
    return a;
}
__device__ __forceinline__ void cpasync16(uint32_t sdst, const float* gsrc) {
    asm volatile("cp.async.cg.shared.global [%0], [%1], 16;\n" :: "r"(sdst), "l"(gsrc));
}

// ================= GEMM (mma.sync tf32, 64x64 warp tiles) =================
// CTA tile 128x128x32, 4 warps (128 threads), warp tile 64x64.
// As: [m][k] stride 36 floats (144B rows) -> conflict-free LDS.32 frags.
// Bs: pair-interleaved: 16 rows (ksj), each 128 float2 pairs (B[k][n],B[k+4][n]),
//     word8(ksj,cc) = ksj*136 + (cc ^ (4*(ksj&3))). LDS.64 conflict-free.
#define AS_STR   36
#define A_BYTES  (128 * AS_STR * 4)     // 18432
#define B_BYTES  (16 * 136 * 8)         // 17408
#define SET_B    (A_BYTES + B_BYTES)    // 35840
#define SMEMSZ   (3 * SET_B)            // 107520

// TWOB: grid.x in [0,16): xb = x&7 N-tile, sel = x>>3 picks (B1,C1,bias1)/(B2,C2,bias2)
// DUAL: K=2048 over (A1,B1) then (A2,B2); epilogue adds bias1+bias2+resid
template <bool TWOB, bool DUAL, bool ROUND2>
__global__ __launch_bounds__(128, 2)
void tc_gemm(const float* __restrict__ A1, const float* __restrict__ A2,
             const float* __restrict__ B1, const float* __restrict__ B2,
             const float* __restrict__ bias1, const float* __restrict__ bias2,
             const float* __restrict__ resid,
             float* __restrict__ C1, float* __restrict__ C2)
{
    constexpr int NK = DUAL ? 64 : 32;
    extern __shared__ float smem[];
    const uint32_t sb = smem_u32(smem);
    const int tid  = threadIdx.x;
    const int lane = tid & 31;
    const int warp = tid >> 5;
    const int wm = warp & 1;        // M half (64 rows)
    const int wn = warp >> 1;       // N half (64 cols)

    const int xb  = TWOB ? (blockIdx.x & 7) : blockIdx.x;
    const int sel = TWOB ? (int)(blockIdx.x >> 3) : 0;
    const int m0 = blockIdx.y * 128;
    const int n0 = xb * 128;
    const float* Bsel    = (TWOB && sel) ? B2 : B1;
    const float* biassel = (TWOB && sel) ? bias2 : bias1;
    float*       Csel    = (TWOB && sel) ? C2 : C1;

    float acc[4][8][4];
#pragma unroll
    for (int i = 0; i < 4; i++)
#pragma unroll
        for (int j = 0; j < 8; j++)
#pragma unroll
            for (int k = 0; k < 4; k++) acc[i][j][k] = 0.f;

    // ---- async tile issue (128 threads) ----
    auto issue = [&](int c) {
        const int slot = c % 3;
        const float* Ap; const float* Bp; int cl;
        if (DUAL && c >= 32) { Ap = A2; Bp = B2;   cl = c - 32; }
        else                 { Ap = A1; Bp = Bsel; cl = c; }
        const int koff = cl * 32;
        const uint32_t sa = sb + slot * SET_B;
        const uint32_t sB = sa + A_BYTES;
#pragma unroll
        for (int i = 0; i < 8; i++) {
            int id = tid + i * 128;
            int r = id >> 3, kq = id & 7;
            cpasync16(sa + (uint32_t)(r * 144 + kq * 16),
                      Ap + (size_t)(m0 + r) * 1024 + koff + kq * 4);
        }
#pragma unroll
        for (int i = 0; i < 8; i++) {
            int id = tid + i * 128;
            int ksj = id >> 6, ch = id & 63;
            uint32_t w8 = (uint32_t)(ksj * 136 + ((2 * ch) ^ ((ksj & 3) << 2)));
            cpasync16(sB + w8 * 8,
                      Bp + (size_t)(cl * 16 + ksj) * 2048 + (size_t)n0 * 2 + ch * 4);
        }
        asm volatile("cp.async.commit_group;\n");
    };

    auto compute = [&](int slot) {
        const float* As = smem + slot * (SET_B / 4);
        const float* Bs = As + (A_BYTES / 4);
        const int r0  = wm * 64 + (lane >> 2);
        const int klB = lane & 3;
        const int ccb = wn * 64 + (lane >> 2);
#pragma unroll
        for (int ks = 0; ks < 4; ks++) {
            const int krow = ks * 8 + klB;
            unsigned af[4][4], bf[8][2];
#pragma unroll
            for (int mt = 0; mt < 4; mt++) {
                int r = r0 + mt * 16;
                af[mt][0] = __float_as_uint(As[r * AS_STR + krow]);
                af[mt][1] = __float_as_uint(As[(r + 8) * AS_STR + krow]);
                af[mt][2] = __float_as_uint(As[r * AS_STR + krow + 4]);
                af[mt][3] = __float_as_uint(As[(r + 8) * AS_STR + krow + 4]);
            }
            const int rowb = (ks * 4 + klB) * 136;
#pragma unroll
            for (int nt = 0; nt < 8; nt++) {
                int cc = ccb + nt * 8;
                int w8 = rowb + (cc ^ (klB << 2));
                float2 bv = *reinterpret_cast<const float2*>(Bs + w8 * 2);
                bf[nt][0] = __float_as_uint(bv.x);
                bf[nt][1] = __float_as_uint(bv.y);
            }
#pragma unroll
            for (int mt = 0; mt < 4; mt++)
#pragma unroll
                for (int nt = 0; nt < 8; nt++)
                    mma8(acc[mt][nt], af[mt], bf[nt]);
        }
    };

    issue(0);
    issue(1);
    for (int k = 0; k < NK; k++) {
        if (k < NK - 1) asm volatile("cp.async.wait_group 1;\n");
        else            asm volatile("cp.async.wait_group 0;\n");
        __syncthreads();
        if (k + 2 < NK) issue(k + 2);
        compute(k % 3);
    }

    // ---- epilogue ----
#pragma unroll
    for (int mt = 0; mt < 4; mt++) {
        int row = m0 + wm * 64 + mt * 16 + (lane >> 2);
#pragma unroll
        for (int nt = 0; nt < 8; nt++) {
            int col = n0 + wn * 64 + nt * 8 + (lane & 3) * 2;
            float b0 = biassel[col], b1 = biassel[col + 1];
            if (DUAL) { b0 += bias2[col]; b1 += bias2[col + 1]; }
            size_t i0 = (size_t)row * 1024 + col;
            size_t i1 = i0 + (size_t)8 * 1024;
            float2 v0 = make_float2(acc[mt][nt][0] + b0, acc[mt][nt][1] + b1);
            float2 v1 = make_float2(acc[mt][nt][2] + b0, acc[mt][nt][3] + b1);
            if (DUAL) {
                float2 x0 = *reinterpret_cast<const float2*>(&resid[i0]);
                float2 x1 = *reinterpret_cast<const float2*>(&resid[i1]);
                v0.x += x0.x; v0.y += x0.y; v1.x += x1.x; v1.y += x1.y;
            }
            if (ROUND2 && sel) {
                v0.x = tf32r(v0.x); v0.y = tf32r(v0.y);
                v1.x = tf32r(v1.x); v1.y = tf32r(v1.y);
            }
            *reinterpret_cast<float2*>(&Csel[i0]) = v0;
            *reinterpret_cast<float2*>(&Csel[i1]) = v1;
        }
    }
}

// ================= weight pair-interleave + tf32 round =================
__global__ void wintl(const float* __restrict__ w0, const float* __restrict__ w1,
                      const float* __restrict__ w2, const float* __restrict__ w3,
                      const float* __restrict__ w4, const float* __restrict__ w5)
{
    const float* srcs[6] = {w0, w1, w2, w3, w4, w5};
    const float* src = srcs[blockIdx.y];
    float* dst = g_Wt + (size_t)blockIdx.y * 1048576;
    const int kg = blockIdx.x;          // 0..127
    const int t = threadIdx.x;          // 0..255
#pragma unroll
    for (int j = 0; j < 4; j++) {
#pragma unroll
        for (int nn = 0; nn < 4; nn++) {
            int n = nn * 256 + t;
            float lo = src[(size_t)(kg * 8 + j) * 1024 + n];
            float hi = src[(size_t)(kg * 8 + j + 4) * 1024 + n];
            float2 o = make_float2(tf32r(lo), tf32r(hi));
            *reinterpret_cast<float2*>(&dst[((size_t)(kg * 4 + j) * 1024 + n) * 2]) = o;
        }
    }
}

// ================= elementwise =================
__global__ void ew_gelu(const float* __restrict__ x) {
    int i = blockIdx.x * 256 + threadIdx.x;
    float4 v = reinterpret_cast<const float4*>(x)[i];
    v.x = tf32r(gelu1(v.x)); v.y = tf32r(gelu1(v.y));
    v.z = tf32r(gelu1(v.z)); v.w = tf32r(gelu1(v.w));
    reinterpret_cast<float4*>(g_xg)[i] = v;
}

// ================= scans (float4 over d; fwd/bwd use SEPARATE carry buffers) =====
// phase 1: local chunk scans. grid (NC, 16): y<8 -> fwd (b=y), y>=8 -> bwd (b=y-8)
__global__ void scan1(const float* __restrict__ a_fwd, const float* __restrict__ a_param) {
    const int d4 = threadIdx.x;             // 0..255
    const int c = blockIdx.x;
    const int zz = blockIdx.y;
    if (zz < 8) {
        const int b = zz;
        float4 a = reinterpret_cast<const float4*>(a_fwd)[d4];
        int idx = ((b * Sc + c * LC) * Dc) / 4 + d4;
        float4 h = make_float4(0.f, 0.f, 0.f, 0.f);
#pragma unroll 4
        for (int t = 0; t < LC; t++) {
            float4 uv = reinterpret_cast<const float4*>(g_u)[idx];
            h.x = fmaf(a.x, h.x, uv.x); h.y = fmaf(a.y, h.y, uv.y);
            h.z = fmaf(a.z, h.z, uv.z); h.w = fmaf(a.w, h.w, uv.w);
            float4 o = make_float4(tf32r(h.x), tf32r(h.y), tf32r(h.z), tf32r(h.w));
            reinterpret_cast<float4*>(g_u)[idx] = o;
            idx += 256;
        }
        reinterpret_cast<float4*>(g_cV)[(b * NC + c) * 256 + d4] = h;
    } else {
        const int b = zz - 8;
        float4 ap = reinterpret_cast<const float4*>(a_param)[d4];
        float4 sp = make_float4(log1pf(expf(ap.x)), log1pf(expf(ap.y)),
                                log1pf(expf(ap.z)), log1pf(expf(ap.w)));
        int idx = ((b * Sc + c * LC + LC - 1) * Dc) / 4 + d4;
        float4 h = make_float4(0.f, 0.f, 0.f, 0.f);
        float4 P = make_float4(1.f, 1.f, 1.f, 1.f);
#pragma unroll 4
        for (int t = 0; t < LC; t++) {
            float4 pv = reinterpret_cast<const float4*>(g_p)[idx];
            float4 qv = reinterpret_cast<const float4*>(g_q)[idx];
            float4 vv = reinterpret_cast<const float4*>(g_v)[idx];
            float4 ao, ho;
#define GB(PV,QV,VV,SP,H,PP,AO,HO) { \
            float gx = sigmoidf(PV); float ga = sigmoidf(QV); \
            float a_ = expf(-8.f * ga * (SP)); \
            float si = sqrtf(fmaxf(1.f - a_*a_, 0.f)) * gx * (VV); \
            H = fmaf(a_, H, si); PP *= a_; AO = a_; HO = tf32r(H); }
            GB(pv.x, qv.x, vv.x, sp.x, h.x, P.x, ao.x, ho.x)
            GB(pv.y, qv.y, vv.y, sp.y, h.y, P.y, ao.y, ho.y)
            GB(pv.z, qv.z, vv.z, sp.z, h.z, P.z, ao.z, ho.z)
            GB(pv.w, qv.w, vv.w, sp.w, h.w, P.w, ao.w, ho.w)
#undef GB
            reinterpret_cast<float4*>(g_q)[idx] = ao;
            reinterpret_cast<float4*>(g_p)[idx] = ho;
            idx -= 256;
        }
        int o = (b * NC + c) * 256 + d4;
        reinterpret_cast<float4*>(g_cVb)[o] = h;
        reinterpret_cast<float4*>(g_cP)[o] = P;
    }
}

// phase 2: carry prefix across chunks. 64 blocks x 256: first half fwd, second bwd
__global__ void scan2(const float* __restrict__ a_fwd) {
    int g = blockIdx.x * 256 + threadIdx.x;
    if (g < 8192) {
        int b = g >> 10, d = g & 1023;
        float a = a_fwd[d];
        float aL = a;
#pragma unroll
        for (int i = 0; i < 7; i++) aL *= aL;     // a^128
        float H = 0.f;
        for (int c = 0; c < NC; c++) {
            int o = (b * NC + c) * Dc + d;
            float cv = g_cV[o];
            g_cI[o] = H;
            H = fmaf(aL, H, cv);
        }
    } else {
        g -= 8192;
        int b = g >> 10, d = g & 1023;
        float H = 0.f;
        for (int c = NC - 1; c >= 0; c--) {
            int o = (b * NC + c) * Dc + d;
            float cv = g_cVb[o], cp = g_cP[o];
            g_cIb[o] = H;
            H = fmaf(cp, H, cv);
        }
    }
}

// phase 3: apply carries. grid (NC, 16)
__global__ void scan3(const float* __restrict__ a_fwd) {
    const int d4 = threadIdx.x;
    const int c = blockIdx.x;
    const int zz = blockIdx.y;
    if (zz < 8) {
        if (c == 0) return;
        const int b = zz;
        float4 a = reinterpret_cast<const float4*>(a_fwd)[d4];
        float4 H = reinterpret_cast<const float4*>(g_cI)[(b * NC + c) * 256 + d4];
        int idx = ((b * Sc + c * LC) * Dc) / 4 + d4;
        float4 pw = a;
#pragma unroll 4
        for (int t = 0; t < LC; t++) {
            float4 uv = reinterpret_cast<const float4*>(g_u)[idx];
            uv.x = tf32r(fmaf(pw.x, H.x, uv.x)); uv.y = tf32r(fmaf(pw.y, H.y, uv.y));
            uv.z = tf32r(fmaf(pw.z, H.z, uv.z)); uv.w = tf32r(fmaf(pw.w, H.w, uv.w));
            reinterpret_cast<float4*>(g_u)[idx] = uv;
            pw.x *= a.x; pw.y *= a.y; pw.z *= a.z; pw.w *= a.w;
            idx += 256;
        }
    } else {
        if (c == NC - 1) return;
        const int b = zz - 8;
        float4 H = reinterpret_cast<const float4*>(g_cIb)[(b * NC + c) * 256 + d4];
        int idx = ((b * Sc + c * LC + LC - 1) * Dc) / 4 + d4;
        float4 P = make_float4(1.f, 1.f, 1.f, 1.f);
#pragma unroll 4
        for (int t = 0; t < LC; t++) {
            float4 at = reinterpret_cast<const float4*>(g_q)[idx];
            float4 pv = reinterpret_cast<const float4*>(g_p)[idx];
            P.x *= at.x; P.y *= at.y; P.z *= at.z; P.w *= at.w;
            pv.x = tf32r(fmaf(P.x, H.x, pv.x)); pv.y = tf32r(fmaf(P.y, H.y, pv.y));
            pv.z = tf32r(fmaf(P.z, H.z, pv.z)); pv.w = tf32r(fmaf(P.w, H.w, pv.w));
            reinterpret_cast<float4*>(g_p)[idx] = pv;
            idx -= 256;
        }
    }
}

// ================= launch =================
extern "C" void kernel_launch(void* const* d_in, const int* in_sizes, int n_in,
                              void* d_out, int out_size)
{
    const float* x       = (const float*)d_in[0];
    const float* a_fwd   = (const float*)d_in[1];
    const float* Wf1     = (const float*)d_in[2];
    const float* bf1     = (const float*)d_in[3];
    const float* Wf2     = (const float*)d_in[4];
    const float* bf2     = (const float*)d_in[5];
    const float* Wbx     = (const float*)d_in[6];
    const float* bbx     = (const float*)d_in[7];
    const float* Wgx     = (const float*)d_in[8];
    const float* bgx     = (const float*)d_in[9];
    const float* Wga     = (const float*)d_in[10];
    const float* bga     = (const float*)d_in[11];
    const float* a_param = (const float*)d_in[12];
    const float* Wb2     = (const float*)d_in[13];
    const float* bb2     = (const float*)d_in[14];
    float* out = (float*)d_out;

    float *xg, *u, *v, *p, *q, *wt;
    cudaGetSymbolAddress((void**)&xg, g_xg);
    cudaGetSymbolAddress((void**)&u,  g_u);
    cudaGetSymbolAddress((void**)&v,  g_v);
    cudaGetSymbolAddress((void**)&p,  g_p);
    cudaGetSymbolAddress((void**)&q,  g_q);
    cudaGetSymbolAddress((void**)&wt, g_Wt);
    const float* Wr_f1 = wt + 0u * 1048576;
    const float* Wr_bx = wt + 1u * 1048576;
    const float* Wr_gx = wt + 2u * 1048576;
    const float* Wr_ga = wt + 3u * 1048576;
    const float* Wr_f2 = wt + 4u * 1048576;
    const float* Wr_b2 = wt + 5u * 1048576;

    cudaFuncSetAttribute(tc_gemm<true,  false, true>,  cudaFuncAttributeMaxDynamicSharedMemorySize, SMEMSZ);
    cudaFuncSetAttribute(tc_gemm<true,  false, false>, cudaFuncAttributeMaxDynamicSharedMemorySize, SMEMSZ);
    cudaFuncSetAttribute(tc_gemm<false, true,  false>, cudaFuncAttributeMaxDynamicSharedMemorySize, SMEMSZ);

    dim3 gp(16, 256);         // pair: 2x N-tiles x M-tiles
    dim3 gf(8, 256);          // final
    dim3 gsc(NC, 16);         // chunks x (8 fwd + 8 bwd)

    // pair-interleave + round weights
    wintl<<<dim3(128, 6), 256>>>(Wf1, Wbx, Wgx, Wga, Wf2, Wb2);
    // xg = tf32(gelu(x))
    ew_gelu<<<NE / 4 / 256, 256>>>(x);
    // u = xg@Wf1+bf1 ; v = tf32(xg@Wbx+bbx)
    tc_gemm<true, false, true><<<gp, 128, SMEMSZ>>>(xg, nullptr, Wr_f1, Wr_bx, bf1, bbx, nullptr, u, v);
    // p = v@Wgx+bgx ; q = v@Wga+bga
    tc_gemm<true, false, false><<<gp, 128, SMEMSZ>>>(v, nullptr, Wr_gx, Wr_ga, bgx, bga, nullptr, p, q);
    // scans: local (fwd u; fused gates + bwd p/q), carries, correction
    scan1<<<gsc, 256>>>(a_fwd, a_param);
    scan2<<<64, 256>>>(a_fwd);
    scan3<<<gsc, 256>>>(a_fwd);
    // out = hf@Wf2 + hb@Wb2 + bf2 + bb2 + x
    tc_gemm<false, true, false><<<gf, 128, SMEMSZ>>>(u, p, Wr_f2, Wr_b2, bf2, bb2, x, out, nullptr);
}

// round 9
// speedup vs baseline: 3.1552x; 1.7496x over previous
#include <cuda_runtime.h>
#include <cuda_fp16.h>
#include <cstdint>

// Problem constants
#define Bc   8
#define Sc   4096
#define Dc   1024
#define Mtot 32768            // B*S
#define NE   33554432         // Mtot*Dc elements
#define NC   32               // scan chunks
#define LC   128              // chunk length (NC*LC == Sc)

// -------- scratch (device globals: allocation-free) --------
__device__ __align__(16) float  g_u [NE];   // u (fp32, scan in place)
__device__ __align__(16) float  g_p [NE];   // gate_x pre -> hb local (fp32)
__device__ __align__(16) float  g_q [NE];   // gate_a pre -> a (fp32)
__device__ __align__(16) __half g_xh[NE];   // gelu(x) fp16
__device__ __align__(16) __half g_vh[NE];   // v fp16
__device__ __align__(16) __half g_uh[NE];   // hf fp16 (final GEMM input)
__device__ __align__(16) __half g_ph[NE];   // hb fp16 (final GEMM input)
__device__ __align__(16) __half g_Wh[6 * 1024 * 1024]; // frag-pair-packed fp16 weights
__device__ __align__(16) float g_cV [Bc*NC*Dc];   // fwd carries
__device__ __align__(16) float g_cI [Bc*NC*Dc];   // fwd prefixes
__device__ __align__(16) float g_cVb[Bc*NC*Dc];   // bwd carries
__device__ __align__(16) float g_cP [Bc*NC*Dc];   // bwd chunk products
__device__ __align__(16) float g_cIb[Bc*NC*Dc];   // bwd prefixes

// ================= helpers =================
__device__ __forceinline__ void mma16(float* c, const unsigned* a, const unsigned* b) {
    asm volatile(
        "mma.sync.aligned.m16n8k16.row.col.f32.f16.f16.f32 "
        "{%0,%1,%2,%3}, {%4,%5,%6,%7}, {%8,%9}, {%0,%1,%2,%3};\n"
        : "+f"(c[0]), "+f"(c[1]), "+f"(c[2]), "+f"(c[3])
        : "r"(a[0]), "r"(a[1]), "r"(a[2]), "r"(a[3]), "r"(b[0]), "r"(b[1]));
}
__device__ __forceinline__ float gelu1(float x) {
    const float c = 0.7978845608028654f;
    float t = tanhf(c * (x + 0.044715f * x * x * x));
    return 0.5f * x * (1.f + t);
}
__device__ __forceinline__ float sigmoidf(float x) { return 1.f / (1.f + expf(-x)); }
__device__ __forceinline__ uint32_t smem_u32(const void* p) {
    uint32_t a;
    asm("{ .reg .u64 t; cvta.to.shared.u64 t, %1; cvt.u32.u64 %0, t; }" : "=r"(a) : "l"(p));
    return a;
}
__device__ __forceinline__ void cpasync16(uint32_t sdst, const void* gsrc) {
    asm volatile("cp.async.cg.shared.global [%0], [%1], 16;\n" :: "r"(sdst), "l"(gsrc));
}

// ================= GEMM (fp16 mma.sync m16n8k16, 64x64 warp tiles, BK=64) ========
// CTA tile 128x128x64, 4 warps, warp tile 64x64.
// As: fp16 [m][k] rows padded to 72 halfs (144B) -> LDS.32 frags conflict-free.
// Bs: frag-pair-packed: 16 rows (ksj = kk*4+j), each 128 n-entries of 8B
//     {B[k0][n],B[k0+1][n],B[k0+8][n],B[k0+9][n]}, k0 = kk*16 + 2j.
//     word8(ksj,n) = ksj*136 + (n ^ ((ksj&3)<<2)). One LDS.64 per B frag.
#define A_BYTES  (128 * 144)            // 18432
#define B_BYTES  (16 * 136 * 8)         // 17408
#define SET_B    (A_BYTES + B_BYTES)    // 35840
#define SMEMSZ   (3 * SET_B)            // 107520

// TWOB: grid.x in [0,16): xb = x&7 N-tile, sel = x>>3 picks (B1,C1,bias1)/(B2,C2,bias2)
// DUAL: K=2048 over (A1,B1) then (A2,B2); epilogue adds bias1+bias2+resid
// C2H : C2 output stored as fp16
template <bool TWOB, bool DUAL, bool C2H>
__global__ __launch_bounds__(128, 2)
void hgemm(const __half* __restrict__ A1, const __half* __restrict__ A2,
           const __half* __restrict__ B1, const __half* __restrict__ B2,
           const float* __restrict__ bias1, const float* __restrict__ bias2,
           const float* __restrict__ resid,
           float* __restrict__ C1, void* __restrict__ C2v)
{
    constexpr int NK = DUAL ? 32 : 16;       // K-tiles of 64
    extern __shared__ float smem[];
    const uint32_t sb = smem_u32(smem);
    const int tid  = threadIdx.x;
    const int lane = tid & 31;
    const int warp = tid >> 5;
    const int wm = warp & 1;        // M half (64 rows)
    const int wn = warp >> 1;       // N half (64 cols)

    const int xb  = TWOB ? (blockIdx.x & 7) : blockIdx.x;
    const int sel = TWOB ? (int)(blockIdx.x >> 3) : 0;
    const int m0 = blockIdx.y * 128;
    const int n0 = xb * 128;
    const __half* Bsel   = (TWOB && sel) ? B2 : B1;
    const float* biassel = (TWOB && sel) ? bias2 : bias1;

    float acc[4][8][4];
#pragma unroll
    for (int i = 0; i < 4; i++)
#pragma unroll
        for (int j = 0; j < 8; j++)
#pragma unroll
            for (int k = 0; k < 4; k++) acc[i][j][k] = 0.f;

    // ---- async tile issue (128 threads) ----
    auto issue = [&](int c) {
        const int slot = c % 3;
        const __half* Ap; const __half* Bp; int cl;
        if (DUAL && c >= 16) { Ap = A2; Bp = B2;   cl = c - 16; }
        else                 { Ap = A1; Bp = Bsel; cl = c; }
        const uint32_t sa = sb + slot * SET_B;
        const uint32_t sB = sa + A_BYTES;
        // A: 128 rows x 64 fp16 (128B) -> 144B-stride rows
#pragma unroll
        for (int i = 0; i < 8; i++) {
            int id = tid + i * 128;
            int r = id >> 3, kq = id & 7;
            cpasync16(sa + (uint32_t)(r * 144 + kq * 16),
                      Ap + (size_t)(m0 + r) * 1024 + cl * 64 + kq * 8);
        }
        // B: 16 packed rows x 128 n x 8B; global row stride 4096 halfs
#pragma unroll
        for (int i = 0; i < 8; i++) {
            int id = tid + i * 128;
            int ksj = id >> 6, ch = id & 63;
            uint32_t w8 = (uint32_t)(ksj * 136 + ((2 * ch) ^ ((ksj & 3) << 2)));
            cpasync16(sB + w8 * 8,
                      Bp + (size_t)(cl * 16 + ksj) * 4096 + (size_t)n0 * 4 + ch * 8);
        }
        asm volatile("cp.async.commit_group;\n");
    };

    auto compute = [&](int slot) {
        const uint32_t* Asw = (const uint32_t*)((const char*)smem + slot * SET_B);
        const uint2*    Bs2 = (const uint2*)((const char*)smem + slot * SET_B + A_BYTES);
        const int r0  = wm * 64 + (lane >> 2);
        const int j   = lane & 3;
        const int ccb = wn * 64 + (lane >> 2);
#pragma unroll
        for (int kk = 0; kk < 4; kk++) {
            unsigned af[4][4], bf[8][2];
#pragma unroll
            for (int mt = 0; mt < 4; mt++) {
                int r = r0 + mt * 16;
                int w0 = r * 36 + kk * 8 + j;
                int w1 = (r + 8) * 36 + kk * 8 + j;
                af[mt][0] = Asw[w0];
                af[mt][1] = Asw[w1];
                af[mt][2] = Asw[w0 + 4];
                af[mt][3] = Asw[w1 + 4];
            }
            const int rowb = (kk * 4 + j) * 136;
#pragma unroll
            for (int nt = 0; nt < 8; nt++) {
                int cc = ccb + nt * 8;
                uint2 bv = Bs2[rowb + (cc ^ (j << 2))];
                bf[nt][0] = bv.x;
                bf[nt][1] = bv.y;
            }
#pragma unroll
            for (int mt = 0; mt < 4; mt++)
#pragma unroll
                for (int nt = 0; nt < 8; nt++)
                    mma16(acc[mt][nt], af[mt], bf[nt]);
        }
    };

    issue(0);
    issue(1);
    for (int k = 0; k < NK; k++) {
        if (k < NK - 1) asm volatile("cp.async.wait_group 1;\n");
        else            asm volatile("cp.async.wait_group 0;\n");
        __syncthreads();
        if (k + 2 < NK) issue(k + 2);
        compute(k % 3);
    }

    // ---- epilogue ----
#pragma unroll
    for (int mt = 0; mt < 4; mt++) {
        int row = m0 + wm * 64 + mt * 16 + (lane >> 2);
#pragma unroll
        for (int nt = 0; nt < 8; nt++) {
            int col = n0 + wn * 64 + nt * 8 + (lane & 3) * 2;
            float b0 = biassel[col], b1 = biassel[col + 1];
            if (DUAL) { b0 += bias2[col]; b1 += bias2[col + 1]; }
            size_t i0 = (size_t)row * 1024 + col;
            size_t i1 = i0 + (size_t)8 * 1024;
            float2 v0 = make_float2(acc[mt][nt][0] + b0, acc[mt][nt][1] + b1);
            float2 v1 = make_float2(acc[mt][nt][2] + b0, acc[mt][nt][3] + b1);
            if (DUAL) {
                float2 x0 = *reinterpret_cast<const float2*>(&resid[i0]);
                float2 x1 = *reinterpret_cast<const float2*>(&resid[i1]);
                v0.x += x0.x; v0.y += x0.y; v1.x += x1.x; v1.y += x1.y;
            }
            if (TWOB && sel) {
                if (C2H) {
                    __half* C2h = (__half*)C2v;
                    *reinterpret_cast<__half2*>(&C2h[i0]) = __floats2half2_rn(v0.x, v0.y);
                    *reinterpret_cast<__half2*>(&C2h[i1]) = __floats2half2_rn(v1.x, v1.y);
                } else {
                    float* C2f = (float*)C2v;
                    *reinterpret_cast<float2*>(&C2f[i0]) = v0;
                    *reinterpret_cast<float2*>(&C2f[i1]) = v1;
                }
            } else {
                *reinterpret_cast<float2*>(&C1[i0]) = v0;
                *reinterpret_cast<float2*>(&C1[i1]) = v1;
            }
        }
    }
}

// ================= weight frag-pair pack to fp16 =================
// dst[(kg*4+j)*4096 + n*4 + e] = fp16(W[kg*16 + 2j + (e>>1)*8 + (e&1)][n])
__global__ void wpack(const float* __restrict__ w0, const float* __restrict__ w1,
                      const float* __restrict__ w2, const float* __restrict__ w3,
                      const float* __restrict__ w4, const float* __restrict__ w5)
{
    const float* srcs[6] = {w0, w1, w2, w3, w4, w5};
    const float* src = srcs[blockIdx.y];
    __half* dst = g_Wh + (size_t)blockIdx.y * 1048576;
    const int kg = blockIdx.x;          // 0..63
    const int t = threadIdx.x;          // 0..255
#pragma unroll
    for (int j = 0; j < 4; j++) {
#pragma unroll
        for (int nn = 0; nn < 4; nn++) {
            int n = nn * 256 + t;
            float f0 = src[(size_t)(kg * 16 + 2 * j    ) * 1024 + n];
            float f1 = src[(size_t)(kg * 16 + 2 * j + 1) * 1024 + n];
            float f2 = src[(size_t)(kg * 16 + 2 * j + 8) * 1024 + n];
            float f3 = src[(size_t)(kg * 16 + 2 * j + 9) * 1024 + n];
            __half2 p0 = __floats2half2_rn(f0, f1);
            __half2 p1 = __floats2half2_rn(f2, f3);
            uint2 o;
            o.x = *reinterpret_cast<uint32_t*>(&p0);
            o.y = *reinterpret_cast<uint32_t*>(&p1);
            *reinterpret_cast<uint2*>(&dst[((size_t)(kg * 4 + j) * 1024 + n) * 4]) = o;
        }
    }
}

// ================= elementwise =================
__global__ void ew_gelu(const float* __restrict__ x) {
    int i = blockIdx.x * 256 + threadIdx.x;
    float4 v = reinterpret_cast<const float4*>(x)[i];
    __half2 h0 = __floats2half2_rn(gelu1(v.x), gelu1(v.y));
    __half2 h1 = __floats2half2_rn(gelu1(v.z), gelu1(v.w));
    uint2 o;
    o.x = *reinterpret_cast<uint32_t*>(&h0);
    o.y = *reinterpret_cast<uint32_t*>(&h1);
    reinterpret_cast<uint2*>(g_xh)[i] = o;
}

// ================= scans (float4 over d; separate fwd/bwd carry buffers) =========
// phase 1: local chunk scans. grid (NC, 16): y<8 -> fwd (b=y), y>=8 -> bwd (b=y-8)
__global__ void scan1(const float* __restrict__ a_fwd, const float* __restrict__ a_param) {
    const int d4 = threadIdx.x;             // 0..255
    const int c = blockIdx.x;
    const int zz = blockIdx.y;
    if (zz < 8) {
        const int b = zz;
        float4 a = reinterpret_cast<const float4*>(a_fwd)[d4];
        int idx = ((b * Sc + c * LC) * Dc) / 4 + d4;
        float4 h = make_float4(0.f, 0.f, 0.f, 0.f);
#pragma unroll 4
        for (int t = 0; t < LC; t++) {
            float4 uv = reinterpret_cast<const float4*>(g_u)[idx];
            h.x = fmaf(a.x, h.x, uv.x); h.y = fmaf(a.y, h.y, uv.y);
            h.z = fmaf(a.z, h.z, uv.z); h.w = fmaf(a.w, h.w, uv.w);
            reinterpret_cast<float4*>(g_u)[idx] = h;
            idx += 256;
        }
        reinterpret_cast<float4*>(g_cV)[(b * NC + c) * 256 + d4] = h;
    } else {
        const int b = zz - 8;
        float4 ap = reinterpret_cast<const float4*>(a_param)[d4];
        float4 sp = make_float4(log1pf(expf(ap.x)), log1pf(expf(ap.y)),
                                log1pf(expf(ap.z)), log1pf(expf(ap.w)));
        int idx = ((b * Sc + c * LC + LC - 1) * Dc) / 4 + d4;
        float4 h = make_float4(0.f, 0.f, 0.f, 0.f);
        float4 P = make_float4(1.f, 1.f, 1.f, 1.f);
#pragma unroll 4
        for (int t = 0; t < LC; t++) {
            float4 pv = reinterpret_cast<const float4*>(g_p)[idx];
            float4 qv = reinterpret_cast<const float4*>(g_q)[idx];
            uint2 vr = reinterpret_cast<const uint2*>(g_vh)[idx];
            __half2 vh0 = *reinterpret_cast<__half2*>(&vr.x);
            __half2 vh1 = *reinterpret_cast<__half2*>(&vr.y);
            float4 vv = make_float4(__low2float(vh0), __high2float(vh0),
                                    __low2float(vh1), __high2float(vh1));
            float4 ao;
#define GB(PV,QV,VV,SP,H,PP,AO) { \
            float gx = sigmoidf(PV); float ga = sigmoidf(QV); \
            float a_ = expf(-8.f * ga * (SP)); \
            float si = sqrtf(fmaxf(1.f - a_*a_, 0.f)) * gx * (VV); \
            H = fmaf(a_, H, si); PP *= a_; AO = a_; }
            GB(pv.x, qv.x, vv.x, sp.x, h.x, P.x, ao.x)
            GB(pv.y, qv.y, vv.y, sp.y, h.y, P.y, ao.y)
            GB(pv.z, qv.z, vv.z, sp.z, h.z, P.z, ao.z)
            GB(pv.w, qv.w, vv.w, sp.w, h.w, P.w, ao.w)
#undef GB
            reinterpret_cast<float4*>(g_q)[idx] = ao;
            reinterpret_cast<float4*>(g_p)[idx] = h;
            idx -= 256;
        }
        int o = (b * NC + c) * 256 + d4;
        reinterpret_cast<float4*>(g_cVb)[o] = h;
        reinterpret_cast<float4*>(g_cP)[o] = P;
    }
}

// phase 2: carry prefix across chunks. 64 blocks x 256: first half fwd, second bwd
__global__ void scan2(const float* __restrict__ a_fwd) {
    int g = blockIdx.x * 256 + threadIdx.x;
    if (g < 8192) {
        int b = g >> 10, d = g & 1023;
        float a = a_fwd[d];
        float aL = a;
#pragma unroll
        for (int i = 0; i < 7; i++) aL *= aL;     // a^128
        float H = 0.f;
        for (int c = 0; c < NC; c++) {
            int o = (b * NC + c) * Dc + d;
            float cv = g_cV[o];
            g_cI[o] = H;
            H = fmaf(aL, H, cv);
        }
    } else {
        g -= 8192;
        int b = g >> 10, d = g & 1023;
        float H = 0.f;
        for (int c = NC - 1; c >= 0; c--) {
            int o = (b * NC + c) * Dc + d;
            float cv = g_cVb[o], cp = g_cP[o];
            g_cIb[o] = H;
            H = fmaf(cp, H, cv);
        }
    }
}

// phase 3: apply carries, emit fp16 hf/hb. grid (NC, 16)
__global__ void scan3(const float* __restrict__ a_fwd) {
    const int d4 = threadIdx.x;
    const int c = blockIdx.x;
    const int zz = blockIdx.y;
    if (zz < 8) {
        const int b = zz;
        float4 a = reinterpret_cast<const float4*>(a_fwd)[d4];
        float4 H = reinterpret_cast<const float4*>(g_cI)[(b * NC + c) * 256 + d4];
        int idx = ((b * Sc + c * LC) * Dc) / 4 + d4;
        float4 pw = a;
#pragma unroll 4
        for (int t = 0; t < LC; t++) {
            float4 uv = reinterpret_cast<const float4*>(g_u)[idx];
            uv.x = fmaf(pw.x, H.x, uv.x); uv.y = fmaf(pw.y, H.y, uv.y);
            uv.z = fmaf(pw.z, H.z, uv.z); uv.w = fmaf(pw.w, H.w, uv.w);
            __half2 h0 = __floats2half2_rn(uv.x, uv.y);
            __half2 h1 = __floats2half2_rn(uv.z, uv.w);
            uint2 o;
            o.x = *reinterpret_cast<uint32_t*>(&h0);
            o.y = *reinterpret_cast<uint32_t*>(&h1);
            reinterpret_cast<uint2*>(g_uh)[idx] = o;
            pw.x *= a.x; pw.y *= a.y; pw.z *= a.z; pw.w *= a.w;
            idx += 256;
        }
    } else {
        const int b = zz - 8;
        float4 H = reinterpret_cast<const float4*>(g_cIb)[(b * NC + c) * 256 + d4];
        int idx = ((b * Sc + c * LC + LC - 1) * Dc) / 4 + d4;
        float4 P = make_float4(1.f, 1.f, 1.f, 1.f);
#pragma unroll 4
        for (int t = 0; t < LC; t++) {
            float4 at = reinterpret_cast<const float4*>(g_q)[idx];
            float4 pv = reinterpret_cast<const float4*>(g_p)[idx];
            P.x *= at.x; P.y *= at.y; P.z *= at.z; P.w *= at.w;
            pv.x = fmaf(P.x, H.x, pv.x); pv.y = fmaf(P.y, H.y, pv.y);
            pv.z = fmaf(P.z, H.z, pv.z); pv.w = fmaf(P.w, H.w, pv.w);
            __half2 h0 = __floats2half2_rn(pv.x, pv.y);
            __half2 h1 = __floats2half2_rn(pv.z, pv.w);
            uint2 o;
            o.x = *reinterpret_cast<uint32_t*>(&h0);
            o.y = *reinterpret_cast<uint32_t*>(&h1);
            reinterpret_cast<uint2*>(g_ph)[idx] = o;
            idx -= 256;
        }
    }
}

// ================= launch =================
extern "C" void kernel_launch(void* const* d_in, const int* in_sizes, int n_in,
                              void* d_out, int out_size)
{
    const float* x       = (const float*)d_in[0];
    const float* a_fwd   = (const float*)d_in[1];
    const float* Wf1     = (const float*)d_in[2];
    const float* bf1     = (const float*)d_in[3];
    const float* Wf2     = (const float*)d_in[4];
    const float* bf2     = (const float*)d_in[5];
    const float* Wbx     = (const float*)d_in[6];
    const float* bbx     = (const float*)d_in[7];
    const float* Wgx     = (const float*)d_in[8];
    const float* bgx     = (const float*)d_in[9];
    const float* Wga     = (const float*)d_in[10];
    const float* bga     = (const float*)d_in[11];
    const float* a_param = (const float*)d_in[12];
    const float* Wb2     = (const float*)d_in[13];
    const float* bb2     = (const float*)d_in[14];
    float* out = (float*)d_out;

    float *u, *p, *q;
    __half *xh, *vh, *uh, *ph, *wh;
    cudaGetSymbolAddress((void**)&u,  g_u);
    cudaGetSymbolAddress((void**)&p,  g_p);
    cudaGetSymbolAddress((void**)&q,  g_q);
    cudaGetSymbolAddress((void**)&xh, g_xh);
    cudaGetSymbolAddress((void**)&vh, g_vh);
    cudaGetSymbolAddress((void**)&uh, g_uh);
    cudaGetSymbolAddress((void**)&ph, g_ph);
    cudaGetSymbolAddress((void**)&wh, g_Wh);
    const __half* Wh_f1 = wh + 0u * 1048576;
    const __half* Wh_bx = wh + 1u * 1048576;
    const __half* Wh_gx = wh + 2u * 1048576;
    const __half* Wh_ga = wh + 3u * 1048576;
    const __half* Wh_f2 = wh + 4u * 1048576;
    const __half* Wh_b2 = wh + 5u * 1048576;

    cudaFuncSetAttribute(hgemm<true,  false, true>,  cudaFuncAttributeMaxDynamicSharedMemorySize, SMEMSZ);
    cudaFuncSetAttribute(hgemm<true,  false, false>, cudaFuncAttributeMaxDynamicSharedMemorySize, SMEMSZ);
    cudaFuncSetAttribute(hgemm<false, true,  false>, cudaFuncAttributeMaxDynamicSharedMemorySize, SMEMSZ);

    dim3 gp(16, 256);         // pair: 2x N-tiles x M-tiles
    dim3 gf(8, 256);          // final
    dim3 gsc(NC, 16);         // chunks x (8 fwd + 8 bwd)

    // pack weights to fp16 fragment-pair layout
    wpack<<<dim3(64, 6), 256>>>(Wf1, Wbx, Wgx, Wga, Wf2, Wb2);
    // xh = fp16(gelu(x))
    ew_gelu<<<NE / 4 / 256, 256>>>(x);
    // u = xh@Wf1+bf1 (fp32) ; vh = fp16(xh@Wbx+bbx)
    hgemm<true, false, true><<<gp, 128, SMEMSZ>>>(xh, nullptr, Wh_f1, Wh_bx, bf1, bbx, nullptr, u, (void*)vh);
    // p = vh@Wgx+bgx ; q = vh@Wga+bga (both fp32)
    hgemm<true, false, false><<<gp, 128, SMEMSZ>>>(vh, nullptr, Wh_gx, Wh_ga, bgx, bga, nullptr, p, (void*)q);
    // scans: local (fwd u; fused gates + bwd p/q), carries, correction + fp16 emit
    scan1<<<gsc, 256>>>(a_fwd, a_param);
    scan2<<<64, 256>>>(a_fwd);
    scan3<<<gsc, 256>>>(a_fwd);
    // out = hf@Wf2 + hb@Wb2 + bf2 + bb2 + x
    hgemm<false, true, false><<<gf, 128, SMEMSZ>>>(uh, ph, Wh_f2, Wh_b2, bf2, bb2, x, out, nullptr);
}